// round 7
// baseline (speedup 1.0000x reference)
#include <cuda_runtime.h>
#include <cuda_bf16.h>
#include <cstdint>

#define NPTS  32768
#define NB    8
#define PPC   4096
#define DIN   64
#define MCTR  8192
#define KNB   32
#define R2    0.04f

__device__ int      g_nbr[MCTR * KNB];
__device__ unsigned g_valid[MCTR];
// 4 units x (32KB hi plane + 32KB lo plane), pre-swizzled B[n][k] images
__device__ __align__(16) unsigned char g_wimg[4 * 65536];

// ---------------------------------------------------------------------------
// helpers
// ---------------------------------------------------------------------------
__device__ __forceinline__ uint32_t smem_u32(const void* p) {
    uint32_t a;
    asm("{ .reg .u64 t; cvta.to.shared.u64 t, %1; cvt.u32.u64 %0, t; }" : "=r"(a) : "l"(p));
    return a;
}

// swizzled byte offset inside a [128 rows][128 bf16] plane (256B rows,
// 16B-unit XOR by row&7 -> conflict-free ldmatrix)
__device__ __forceinline__ uint32_t poff(uint32_t r, uint32_t c) {
    return r * 256u + ((c * 2u) ^ ((r & 7u) << 4));
}

__device__ __forceinline__ void split2(float a, float b, uint32_t& hi, uint32_t& lo) {
    __nv_bfloat16 ha = __float2bfloat16(a), hb = __float2bfloat16(b);
    float ra = a - __bfloat162float(ha), rb = b - __bfloat162float(hb);
    __nv_bfloat162 H; H.x = ha; H.y = hb;
    __nv_bfloat162 L; L.x = __float2bfloat16(ra); L.y = __float2bfloat16(rb);
    hi = *(uint32_t*)&H;
    lo = *(uint32_t*)&L;
}

#define LDSM4(a, r0, r1, r2, r3) \
    asm volatile("ldmatrix.sync.aligned.m8n8.x4.shared.b16 {%0,%1,%2,%3}, [%4];" \
        : "=r"(r0), "=r"(r1), "=r"(r2), "=r"(r3) : "r"(a))

__device__ __forceinline__ void mma16816(float* c, uint32_t a0, uint32_t a1, uint32_t a2,
                                         uint32_t a3, uint32_t b0, uint32_t b1) {
    asm volatile("mma.sync.aligned.m16n8k16.row.col.f32.bf16.bf16.f32 "
        "{%0,%1,%2,%3}, {%4,%5,%6,%7}, {%8,%9}, {%0,%1,%2,%3};"
        : "+f"(c[0]), "+f"(c[1]), "+f"(c[2]), "+f"(c[3])
        : "r"(a0), "r"(a1), "r"(a2), "r"(a3), "r"(b0), "r"(b1));
}

#define CP_ASYNC16(dst, src) \
    asm volatile("cp.async.cg.shared.global [%0], [%1], 16;" :: "r"(dst), "l"(src))
#define CP_COMMIT  asm volatile("cp.async.commit_group;" ::: "memory")
#define CP_WAIT0   asm volatile("cp.async.wait_group 0;" ::: "memory")

// ---------------------------------------------------------------------------
// Weight prep: split fp32 W -> bf16 hi/lo, write pre-swizzled B[n][k] image.
// unit 0: W1 (K padded 67->128), 1: W2, 2: W3[:, :128], 3: W3[:, 128:]
// ---------------------------------------------------------------------------
__global__ void prep_kernel(const float* __restrict__ W1, const float* __restrict__ W2,
                            const float* __restrict__ W3) {
    int t = blockIdx.x * blockDim.x + threadIdx.x;   // 65536
    int u = t >> 14, n = (t >> 7) & 127, k = t & 127;
    float w = 0.0f;
    if (u == 0)      { if (k < 67) w = W1[k * 128 + n]; }
    else if (u == 1) w = W2[k * 128 + n];
    else if (u == 2) w = W3[k * 256 + n];
    else             w = W3[k * 256 + 128 + n];
    __nv_bfloat16 h = __float2bfloat16(w);
    __nv_bfloat16 l = __float2bfloat16(w - __bfloat162float(h));
    uint32_t off = poff(n, k);
    unsigned char* base = g_wimg + u * 65536;
    *(__nv_bfloat16*)(base + off)         = h;
    *(__nv_bfloat16*)(base + 32768 + off) = l;
}

// ---------------------------------------------------------------------------
// KNN kernel: 8 centers/block, cloud pos tile staged to smem as SoA.
// ---------------------------------------------------------------------------
__device__ __forceinline__ unsigned long long warp_max_ull(unsigned long long v) {
#pragma unroll
    for (int o = 16; o; o >>= 1) {
        unsigned long long t = __shfl_xor_sync(0xffffffffu, v, o);
        v = t > v ? t : v;
    }
    return v;
}

#define KNN_SMEM (4 * PPC * 4)

__global__ void __launch_bounds__(256)
knn_kernel(const float* __restrict__ pos,
           const int* __restrict__ batch,
           const int* __restrict__ idx,
           float* __restrict__ posout,
           float* __restrict__ batchout,
           int writeAux)
{
    extern __shared__ float sk[];
    float* px = sk;
    float* py = sk + PPC;
    float* pz = sk + 2 * PPC;
    float* ps = sk + 3 * PPC;

    int tid  = threadIdx.x, wid = tid >> 5, lane = tid & 31;
    int m    = blockIdx.x * 8 + wid;
    int ci   = idx[m];
    int b    = batch[ci];
    int b0   = batch[idx[blockIdx.x * 8]];
    int cb   = b * PPC;
    bool fast = (b == b0);

    // cooperative stage of cloud b0
    {
        const float* pc = pos + (size_t)b0 * PPC * 3;
        for (int i = tid; i < PPC; i += 256) {
            float p0 = pc[3 * i], p1 = pc[3 * i + 1], p2 = pc[3 * i + 2];
            px[i] = p0; py[i] = p1; pz[i] = p2;
            ps[i] = p0 * p0 + p1 * p1 + p2 * p2;
        }
    }
    __syncthreads();

    float c0 = pos[ci * 3 + 0], c1 = pos[ci * 3 + 1], c2 = pos[ci * 3 + 2];
    float cs = c0 * c0 + c1 * c1 + c2 * c2;

    unsigned long long kept   = 0xffffffffffffffffull;
    unsigned long long curmax = 0xffffffffffffffffull;

    for (int base = 0; base < PPC; base += 32) {
        int jj = base + lane;
        int j  = cb + jj;
        float d2;
        if (fast) {
            float dt = c0 * px[jj] + c1 * py[jj] + c2 * pz[jj];
            d2 = (cs + ps[jj]) - 2.0f * dt;
        } else {
            float p0 = pos[j * 3 + 0], p1 = pos[j * 3 + 1], p2 = pos[j * 3 + 2];
            float pss = p0 * p0 + p1 * p1 + p2 * p2;
            float dt = c0 * p0 + c1 * p1 + c2 * p2;
            d2 = (cs + pss) - 2.0f * dt;
        }

        unsigned u   = __float_as_uint(d2);
        unsigned ord = (u & 0x80000000u) ? ~u : (u | 0x80000000u);
        unsigned long long ck = ((unsigned long long)ord << 32) | (unsigned)j;

        unsigned mask = __ballot_sync(0xffffffffu, ck < curmax);
        if (mask) {
            while (mask) {
                int s = __ffs(mask) - 1; mask &= mask - 1;
                unsigned long long cand = __shfl_sync(0xffffffffu, ck, s);
                unsigned long long mx = warp_max_ull(kept);
                if (cand < mx) {
                    unsigned who = __ballot_sync(0xffffffffu, kept == mx);
                    if (lane == (__ffs(who) - 1)) kept = cand;
                }
            }
            curmax = warp_max_ull(kept);
        }
    }

    unsigned nb   = (unsigned)(kept & 0xffffffffu);
    unsigned ordb = (unsigned)(kept >> 32);
    unsigned ub   = (ordb & 0x80000000u) ? (ordb ^ 0x80000000u) : ~ordb;
    float d2v = __uint_as_float(ub);

    g_nbr[m * KNB + lane] = (int)nb;
    unsigned vm = __ballot_sync(0xffffffffu, d2v <= R2);
    if (lane == 0) g_valid[m] = vm;

    if (writeAux) {
        if (lane < 3)   posout[m * 3 + lane] = pos[ci * 3 + lane];
        if (lane == 3)  batchout[m] = (float)b;
    }
}

// ---------------------------------------------------------------------------
// MLP kernel: mma.sync bf16 3-term compensated, fused 3 layers + masked max.
// 8 warps; warp w owns M-rows [16w, 16w+16). 4 centers per block.
// ---------------------------------------------------------------------------
#define OFF_A   8192u
#define OFF_B0  73728u
#define OFF_B1  139264u
#define SMEM_TOTAL 204800

template <int KT>
__device__ __forceinline__ void do_unit_mma(uint32_t a_base, uint32_t alk, uint32_t arx,
                                            uint32_t bufb, uint32_t browo, uint32_t blk,
                                            uint32_t brx, float* acc)
{
#pragma unroll
    for (int kt = 0; kt < KT; kt++) {
        uint32_t k2 = (uint32_t)kt * 32u;
        uint32_t aa = a_base + ((k2 + alk) ^ arx);
        uint32_t ah0, ah1, ah2, ah3, al0, al1, al2, al3;
        LDSM4(aa,         ah0, ah1, ah2, ah3);
        LDSM4(aa + 32768, al0, al1, al2, al3);
#pragma unroll
        for (int np = 0; np < 8; np++) {
            uint32_t ba = bufb + (uint32_t)np * 4096u + browo + ((k2 + blk) ^ brx);
            uint32_t bh0, bh1, bh2, bh3, bl0, bl1, bl2, bl3;
            LDSM4(ba,         bh0, bh1, bh2, bh3);
            LDSM4(ba + 32768, bl0, bl1, bl2, bl3);
            mma16816(&acc[(2 * np)     * 4], ah0, ah1, ah2, ah3, bh0, bh1);
            mma16816(&acc[(2 * np + 1) * 4], ah0, ah1, ah2, ah3, bh2, bh3);
            mma16816(&acc[(2 * np)     * 4], ah0, ah1, ah2, ah3, bl0, bl1);
            mma16816(&acc[(2 * np + 1) * 4], ah0, ah1, ah2, ah3, bl2, bl3);
            mma16816(&acc[(2 * np)     * 4], al0, al1, al2, al3, bh0, bh1);
            mma16816(&acc[(2 * np + 1) * 4], al0, al1, al2, al3, bh2, bh3);
        }
    }
}

__global__ void __launch_bounds__(256, 1)
mlp_kernel(const float* __restrict__ x, const float* __restrict__ pos,
           const int* __restrict__ idx,
           const float* __restrict__ b1, const float* __restrict__ b2,
           const float* __restrict__ b3, float* __restrict__ out)
{
    extern __shared__ char smc[];
    float* bias_s = (float*)smc;           // 512 floats
    float* wmax   = (float*)(smc + 2048);  // 8*128 floats
    uint32_t sb = smem_u32(smc);

    int tid = threadIdx.x, wid = tid >> 5, lane = tid & 31;
    int m0 = blockIdx.x * 4;

    // ---------------- phase 0: feature tile + bias + stage W(unit0) --------
    if (tid < 128) {
        int row = tid;
        int nb  = g_nbr[m0 * KNB + row];
        int ci  = idx[m0 + (row >> 5)];
        const float4* xr = (const float4*)(x + nb * DIN);
#pragma unroll
        for (int i = 0; i < 16; i++) {
            float4 v = __ldg(xr + i);
            uint32_t h0, l0, h1, l1;
            split2(v.x, v.y, h0, l0);
            split2(v.z, v.w, h1, l1);
            uint32_t o0 = poff(row, 4 * i), o1 = poff(row, 4 * i + 2);
            *(uint32_t*)(smc + OFF_A + o0)         = h0;
            *(uint32_t*)(smc + OFF_A + 32768 + o0) = l0;
            *(uint32_t*)(smc + OFF_A + o1)         = h1;
            *(uint32_t*)(smc + OFF_A + 32768 + o1) = l1;
        }
        float r0v = pos[nb * 3 + 0] - pos[ci * 3 + 0];
        float r1v = pos[nb * 3 + 1] - pos[ci * 3 + 1];
        float r2v = pos[nb * 3 + 2] - pos[ci * 3 + 2];
        uint32_t h, l;
        split2(r0v, r1v, h, l);
        { uint32_t o = poff(row, 64);
          *(uint32_t*)(smc + OFF_A + o) = h; *(uint32_t*)(smc + OFF_A + 32768 + o) = l; }
        split2(r2v, 0.0f, h, l);
        { uint32_t o = poff(row, 66);
          *(uint32_t*)(smc + OFF_A + o) = h; *(uint32_t*)(smc + OFF_A + 32768 + o) = l; }
        // zero-pad only cols 68..79 (unit 0 reads k<80; epilogue rewrites all)
#pragma unroll
        for (int c = 68; c < 80; c += 2) {
            uint32_t o = poff(row, c);
            *(uint32_t*)(smc + OFF_A + o) = 0u; *(uint32_t*)(smc + OFF_A + 32768 + o) = 0u;
        }
    } else {
        int j = tid - 128;
        if (j < 32)       ((float4*)bias_s)[j]      = ((const float4*)b1)[j];
        else if (j < 64)  ((float4*)bias_s)[j]      = ((const float4*)b2)[j - 32];
        else              ((float4*)bias_s)[j]      = ((const float4*)b3)[j - 64];
        int ct = j;
        const char* src = (const char*)g_wimg;
        for (int i = ct; i < 4096; i += 128)
            CP_ASYNC16(sb + OFF_B0 + i * 16, src + (size_t)i * 16);
    }
    CP_COMMIT;

    // per-warp/lane ldmatrix address constants
    int l7 = lane & 7, lh = (lane >> 3) & 1, lq = lane >> 4;
    int r0w = wid * 16;
    uint32_t arow   = (uint32_t)(r0w + l7 + lh * 8);
    uint32_t a_base = sb + OFF_A + arow * 256u;
    uint32_t arx    = (arow & 7u) << 4;
    uint32_t alk    = (uint32_t)lq * 16u;
    uint32_t browo  = (uint32_t)(l7 + lq * 8) * 256u;
    uint32_t brx    = ((uint32_t)l7 & 7u) << 4;
    uint32_t blk    = (uint32_t)lh * 16u;

    int gid = lane >> 2, tig = lane & 3;

    for (int u = 0; u < 4; u++) {
        CP_WAIT0;
        __syncthreads();   // A tile + B(u) buffer ready for everyone

        // prefetch next unit's weights into the other buffer
        if (u < 3) {
            const char* src = (const char*)g_wimg + (size_t)(u + 1) * 65536;
            uint32_t dst = sb + (((u + 1) & 1) ? OFF_B1 : OFF_B0);
            for (int i = tid; i < 4096; i += 256)
                CP_ASYNC16(dst + i * 16, src + (size_t)i * 16);
            CP_COMMIT;
        }

        uint32_t bufb = sb + ((u & 1) ? OFF_B1 : OFF_B0);
        float acc[64];
#pragma unroll
        for (int i = 0; i < 64; i++) acc[i] = 0.0f;

        if (u == 0) do_unit_mma<5>(a_base, alk, arx, bufb, browo, blk, brx, acc);
        else        do_unit_mma<8>(a_base, alk, arx, bufb, browo, blk, brx, acc);

        __syncthreads();   // all mma reads of A done before epilogue rewrites A

        if (u < 2) {
            int bo = u * 128;
            int rowA = r0w + gid, rowB = rowA + 8;
#pragma unroll
            for (int np = 0; np < 8; np++)
#pragma unroll
                for (int t = 0; t < 2; t++) {
                    int col = np * 16 + t * 8 + 2 * tig;
                    float* c = &acc[(2 * np + t) * 4];
                    float b0v = bias_s[bo + col], b1v = bias_s[bo + col + 1];
                    float v0 = fmaxf(c[0] + b0v, 0.0f), v1 = fmaxf(c[1] + b1v, 0.0f);
                    float v2 = fmaxf(c[2] + b0v, 0.0f), v3 = fmaxf(c[3] + b1v, 0.0f);
                    uint32_t h, l;
                    split2(v0, v1, h, l);
                    { uint32_t o = poff((uint32_t)rowA, (uint32_t)col);
                      *(uint32_t*)(smc + OFF_A + o) = h;
                      *(uint32_t*)(smc + OFF_A + 32768 + o) = l; }
                    split2(v2, v3, h, l);
                    { uint32_t o = poff((uint32_t)rowB, (uint32_t)col);
                      *(uint32_t*)(smc + OFF_A + o) = h;
                      *(uint32_t*)(smc + OFF_A + 32768 + o) = l; }
                }
        } else {
            int half = u - 2;
            int g = wid >> 1;
            unsigned vm = g_valid[m0 + g];
            int bitbase = (wid & 1) * 16;
            bool okA = (vm >> (bitbase + gid)) & 1u;
            bool okB = (vm >> (bitbase + gid + 8)) & 1u;
#pragma unroll
            for (int np = 0; np < 8; np++)
#pragma unroll
                for (int t = 0; t < 2; t++) {
                    int col = np * 16 + t * 8 + 2 * tig;
                    float* c = &acc[(2 * np + t) * 4];
                    float b0v = bias_s[256 + half * 128 + col];
                    float b1v = bias_s[256 + half * 128 + col + 1];
                    float m0v = fmaxf(okA ? fmaxf(c[0] + b0v, 0.0f) : 0.0f,
                                      okB ? fmaxf(c[2] + b0v, 0.0f) : 0.0f);
                    float m1v = fmaxf(okA ? fmaxf(c[1] + b1v, 0.0f) : 0.0f,
                                      okB ? fmaxf(c[3] + b1v, 0.0f) : 0.0f);
#pragma unroll
                    for (int o = 4; o <= 16; o <<= 1) {
                        m0v = fmaxf(m0v, __shfl_xor_sync(0xffffffffu, m0v, o));
                        m1v = fmaxf(m1v, __shfl_xor_sync(0xffffffffu, m1v, o));
                    }
                    if (lane < 4) {
                        wmax[wid * 128 + col]     = m0v;
                        wmax[wid * 128 + col + 1] = m1v;
                    }
                }
            __syncthreads();
            for (int e = tid; e < 512; e += 256) {
                int gg = e >> 7, col = e & 127;
                float v = fmaxf(wmax[(gg * 2) * 128 + col], wmax[(gg * 2 + 1) * 128 + col]);
                out[(size_t)(m0 + gg) * 256 + half * 128 + col] = v;
            }
        }
    }
}

// ---------------------------------------------------------------------------
extern "C" void kernel_launch(void* const* d_in, const int* in_sizes, int n_in,
                              void* d_out, int out_size)
{
    const float* x     = (const float*)d_in[0];
    const float* pos   = (const float*)d_in[1];
    const int*   batch = (const int*)d_in[2];
    const int*   idx   = (const int*)d_in[3];
    const float* W1 = (const float*)d_in[4];
    const float* b1 = (const float*)d_in[5];
    const float* W2 = (const float*)d_in[6];
    const float* b2 = (const float*)d_in[7];
    const float* W3 = (const float*)d_in[8];
    const float* b3 = (const float*)d_in[9];

    float* out = (float*)d_out;
    int writeAux = (out_size >= MCTR * 256 + MCTR * 3 + MCTR) ? 1 : 0;
    float* posout   = out + MCTR * 256;
    float* batchout = posout + MCTR * 3;

    prep_kernel<<<256, 256>>>(W1, W2, W3);

    cudaFuncSetAttribute(knn_kernel, cudaFuncAttributeMaxDynamicSharedMemorySize, KNN_SMEM);
    knn_kernel<<<MCTR / 8, 256, KNN_SMEM>>>(pos, batch, idx, posout, batchout, writeAux);

    cudaFuncSetAttribute(mlp_kernel, cudaFuncAttributeMaxDynamicSharedMemorySize, SMEM_TOTAL);
    mlp_kernel<<<MCTR / 4, 256, SMEM_TOTAL>>>(x, pos, idx, b1, b2, b3, out);
}

// round 8
// speedup vs baseline: 1.3858x; 1.3858x over previous
#include <cuda_runtime.h>
#include <cuda_bf16.h>
#include <cstdint>

#define NPTS  32768
#define NB    8
#define PPC   4096
#define DIN   64
#define MCTR  8192
#define KNB   32
#define R2    0.04f

#define SENT 0xffffffffffffffffull

__device__ int      g_nbr[MCTR * KNB];
__device__ unsigned g_valid[MCTR];
// 4 units x (32KB hi plane + 32KB lo plane), pre-swizzled B[n][k] images
__device__ __align__(16) unsigned char g_wimg[4 * 65536];

// ---------------------------------------------------------------------------
// helpers
// ---------------------------------------------------------------------------
__device__ __forceinline__ uint32_t smem_u32(const void* p) {
    uint32_t a;
    asm("{ .reg .u64 t; cvta.to.shared.u64 t, %1; cvt.u32.u64 %0, t; }" : "=r"(a) : "l"(p));
    return a;
}

// swizzled byte offset inside a [rows][128 bf16] plane (256B rows,
// 16B-unit XOR by row&7 -> conflict-free ldmatrix)
__device__ __forceinline__ uint32_t poff(uint32_t r, uint32_t c) {
    return r * 256u + ((c * 2u) ^ ((r & 7u) << 4));
}

__device__ __forceinline__ void split2(float a, float b, uint32_t& hi, uint32_t& lo) {
    __nv_bfloat16 ha = __float2bfloat16(a), hb = __float2bfloat16(b);
    float ra = a - __bfloat162float(ha), rb = b - __bfloat162float(hb);
    __nv_bfloat162 H; H.x = ha; H.y = hb;
    __nv_bfloat162 L; L.x = __float2bfloat16(ra); L.y = __float2bfloat16(rb);
    hi = *(uint32_t*)&H;
    lo = *(uint32_t*)&L;
}

#define LDSM4(a, r0, r1, r2, r3) \
    asm volatile("ldmatrix.sync.aligned.m8n8.x4.shared.b16 {%0,%1,%2,%3}, [%4];" \
        : "=r"(r0), "=r"(r1), "=r"(r2), "=r"(r3) : "r"(a))

__device__ __forceinline__ void mma16816(float* c, uint32_t a0, uint32_t a1, uint32_t a2,
                                         uint32_t a3, uint32_t b0, uint32_t b1) {
    asm volatile("mma.sync.aligned.m16n8k16.row.col.f32.bf16.bf16.f32 "
        "{%0,%1,%2,%3}, {%4,%5,%6,%7}, {%8,%9}, {%0,%1,%2,%3};"
        : "+f"(c[0]), "+f"(c[1]), "+f"(c[2]), "+f"(c[3])
        : "r"(a0), "r"(a1), "r"(a2), "r"(a3), "r"(b0), "r"(b1));
}

#define CP_ASYNC16(dst, src) \
    asm volatile("cp.async.cg.shared.global [%0], [%1], 16;" :: "r"(dst), "l"(src))
#define CP_COMMIT  asm volatile("cp.async.commit_group;" ::: "memory")
#define CP_WAIT0   asm volatile("cp.async.wait_group 0;" ::: "memory")

// ---------------------------------------------------------------------------
// Weight prep: split fp32 W -> bf16 hi/lo, write pre-swizzled B[n][k] image.
// unit 0: W1 (K padded 67->128), 1: W2, 2: W3[:, :128], 3: W3[:, 128:]
// ---------------------------------------------------------------------------
__global__ void prep_kernel(const float* __restrict__ W1, const float* __restrict__ W2,
                            const float* __restrict__ W3) {
    int t = blockIdx.x * blockDim.x + threadIdx.x;   // 65536
    int u = t >> 14, n = (t >> 7) & 127, k = t & 127;
    float w = 0.0f;
    if (u == 0)      { if (k < 67) w = W1[k * 128 + n]; }
    else if (u == 1) w = W2[k * 128 + n];
    else if (u == 2) w = W3[k * 256 + n];
    else             w = W3[k * 256 + 128 + n];
    __nv_bfloat16 h = __float2bfloat16(w);
    __nv_bfloat16 l = __float2bfloat16(w - __bfloat162float(h));
    uint32_t off = poff(n, k);
    unsigned char* base = g_wimg + u * 65536;
    *(__nv_bfloat16*)(base + off)         = h;
    *(__nv_bfloat16*)(base + 32768 + off) = l;
}

// ---------------------------------------------------------------------------
// KNN kernel: radius-first filter. valid-top32 == nearest min(32,cnt) points
// with d2 <= R2 (within-radius points always rank before out-of-radius ones),
// so only candidates passing the radius test enter the insertion machinery.
// Invalid slots -> center index (masked out of the max aggregation).
// ---------------------------------------------------------------------------
__device__ __forceinline__ unsigned long long warp_max_ull(unsigned long long v) {
#pragma unroll
    for (int o = 16; o; o >>= 1) {
        unsigned long long t = __shfl_xor_sync(0xffffffffu, v, o);
        v = t > v ? t : v;
    }
    return v;
}

__global__ void knn_kernel(const float* __restrict__ pos,
                           const int* __restrict__ batch,
                           const int* __restrict__ idx,
                           float* __restrict__ posout,
                           float* __restrict__ batchout,
                           int writeAux)
{
    int warp = (blockIdx.x * blockDim.x + threadIdx.x) >> 5;
    int lane = threadIdx.x & 31;
    if (warp >= MCTR) return;

    int ci = idx[warp];
    int b  = batch[ci];
    int cb = b * PPC;

    float c0 = pos[ci * 3 + 0], c1 = pos[ci * 3 + 1], c2 = pos[ci * 3 + 2];
    float cs = c0 * c0 + c1 * c1 + c2 * c2;

    unsigned long long kept   = SENT;
    unsigned long long curmax = SENT;

    for (int base = 0; base < PPC; base += 32) {
        int j = cb + base + lane;
        float p0 = pos[j * 3 + 0], p1 = pos[j * 3 + 1], p2 = pos[j * 3 + 2];
        float ps = p0 * p0 + p1 * p1 + p2 * p2;
        float dt = c0 * p0 + c1 * p1 + c2 * p2;
        float d2 = (cs + ps) - 2.0f * dt;   // bit-identical to reference expansion

        unsigned u   = __float_as_uint(d2);
        unsigned ord = (u & 0x80000000u) ? ~u : (u | 0x80000000u);
        unsigned long long ck = ((unsigned long long)ord << 32) | (unsigned)j;

        unsigned mask = __ballot_sync(0xffffffffu, (d2 <= R2) && (ck < curmax));
        if (mask) {
            while (mask) {
                int s = __ffs(mask) - 1; mask &= mask - 1;
                unsigned long long cand = __shfl_sync(0xffffffffu, ck, s);
                unsigned long long mx = warp_max_ull(kept);
                if (cand < mx) {
                    unsigned who = __ballot_sync(0xffffffffu, kept == mx);
                    if (lane == (__ffs(who) - 1)) kept = cand;
                }
            }
            curmax = warp_max_ull(kept);
        }
    }

    unsigned vm = __ballot_sync(0xffffffffu, kept != SENT);
    int nb = (kept != SENT) ? (int)(kept & 0xffffffffu) : ci;

    g_nbr[warp * KNB + lane] = nb;
    if (lane == 0) g_valid[warp] = vm;

    if (writeAux) {
        if (lane < 3)   posout[warp * 3 + lane] = pos[ci * 3 + lane];
        if (lane == 3)  batchout[warp] = (float)b;
    }
}

// ---------------------------------------------------------------------------
// MLP kernel: mma.sync bf16 3-term compensated, fused 3 layers + masked max.
// 512 threads / 16 warps; warp w owns M-rows [16w, 16w+16). 8 centers/block.
// A planes 128KB (hi/lo), single 64KB B buffer; next-unit cp.async issued
// under the epilogue.
// ---------------------------------------------------------------------------
#define OFF_A   16384u
#define A_LO    65536u
#define OFF_B   147456u
#define SMEM_TOTAL 212992

template <int KT>
__device__ __forceinline__ void do_unit_mma(uint32_t a_base, uint32_t alk, uint32_t arx,
                                            uint32_t bufb, uint32_t browo, uint32_t blk,
                                            uint32_t brx, float* acc)
{
#pragma unroll
    for (int kt = 0; kt < KT; kt++) {
        uint32_t k2 = (uint32_t)kt * 32u;
        uint32_t aa = a_base + ((k2 + alk) ^ arx);
        uint32_t ah0, ah1, ah2, ah3, al0, al1, al2, al3;
        LDSM4(aa,        ah0, ah1, ah2, ah3);
        LDSM4(aa + A_LO, al0, al1, al2, al3);
#pragma unroll
        for (int np = 0; np < 8; np++) {
            uint32_t ba = bufb + (uint32_t)np * 4096u + browo + ((k2 + blk) ^ brx);
            uint32_t bh0, bh1, bh2, bh3, bl0, bl1, bl2, bl3;
            LDSM4(ba,         bh0, bh1, bh2, bh3);
            LDSM4(ba + 32768, bl0, bl1, bl2, bl3);
            mma16816(&acc[(2 * np)     * 4], ah0, ah1, ah2, ah3, bh0, bh1);
            mma16816(&acc[(2 * np + 1) * 4], ah0, ah1, ah2, ah3, bh2, bh3);
            mma16816(&acc[(2 * np)     * 4], ah0, ah1, ah2, ah3, bl0, bl1);
            mma16816(&acc[(2 * np + 1) * 4], ah0, ah1, ah2, ah3, bl2, bl3);
            mma16816(&acc[(2 * np)     * 4], al0, al1, al2, al3, bh0, bh1);
            mma16816(&acc[(2 * np + 1) * 4], al0, al1, al2, al3, bh2, bh3);
        }
    }
}

__global__ void __launch_bounds__(512, 1)
mlp_kernel(const float* __restrict__ x, const float* __restrict__ pos,
           const int* __restrict__ idx,
           const float* __restrict__ b1, const float* __restrict__ b2,
           const float* __restrict__ b3, float* __restrict__ out)
{
    extern __shared__ char smc[];
    float* bias_s = (float*)smc;           // 512 floats
    float* wmax   = (float*)(smc + 2048);  // 16*128 floats
    uint32_t sb = smem_u32(smc);

    int tid = threadIdx.x, wid = tid >> 5, lane = tid & 31;
    int m0 = blockIdx.x * 8;

    // ---------------- phase 0: feature tile + bias + stage W(unit0) --------
    if (tid < 256) {
        int row = tid;
        int nb  = g_nbr[m0 * KNB + row];
        int ci  = idx[m0 + (row >> 5)];
        const float4* xr = (const float4*)(x + nb * DIN);
#pragma unroll
        for (int i = 0; i < 16; i++) {
            float4 v = __ldg(xr + i);
            uint32_t h0, l0, h1, l1;
            split2(v.x, v.y, h0, l0);
            split2(v.z, v.w, h1, l1);
            uint32_t o0 = poff(row, 4 * i), o1 = poff(row, 4 * i + 2);
            *(uint32_t*)(smc + OFF_A + o0)        = h0;
            *(uint32_t*)(smc + OFF_A + A_LO + o0) = l0;
            *(uint32_t*)(smc + OFF_A + o1)        = h1;
            *(uint32_t*)(smc + OFF_A + A_LO + o1) = l1;
        }
        float r0v = pos[nb * 3 + 0] - pos[ci * 3 + 0];
        float r1v = pos[nb * 3 + 1] - pos[ci * 3 + 1];
        float r2v = pos[nb * 3 + 2] - pos[ci * 3 + 2];
        uint32_t h, l;
        split2(r0v, r1v, h, l);
        { uint32_t o = poff(row, 64);
          *(uint32_t*)(smc + OFF_A + o) = h; *(uint32_t*)(smc + OFF_A + A_LO + o) = l; }
        split2(r2v, 0.0f, h, l);
        { uint32_t o = poff(row, 66);
          *(uint32_t*)(smc + OFF_A + o) = h; *(uint32_t*)(smc + OFF_A + A_LO + o) = l; }
        // zero-pad only cols 68..79 (unit 0 reads k<80; epilogue rewrites all)
#pragma unroll
        for (int c = 68; c < 80; c += 2) {
            uint32_t o = poff(row, c);
            *(uint32_t*)(smc + OFF_A + o) = 0u; *(uint32_t*)(smc + OFF_A + A_LO + o) = 0u;
        }
    } else {
        int j = tid - 256;
        if (j < 32)       ((float4*)bias_s)[j] = ((const float4*)b1)[j];
        else if (j < 64)  ((float4*)bias_s)[j] = ((const float4*)b2)[j - 32];
        else if (j < 96)  ((float4*)bias_s)[j] = ((const float4*)b3)[j - 64];
        const char* src = (const char*)g_wimg;
        for (int i = j; i < 4096; i += 256)
            CP_ASYNC16(sb + OFF_B + i * 16, src + (size_t)i * 16);
    }
    CP_COMMIT;

    // per-warp/lane ldmatrix address constants
    int l7 = lane & 7, lh = (lane >> 3) & 1, lq = lane >> 4;
    int r0w = wid * 16;
    uint32_t arow   = (uint32_t)(r0w + l7 + lh * 8);
    uint32_t a_base = sb + OFF_A + arow * 256u;
    uint32_t arx    = (arow & 7u) << 4;
    uint32_t alk    = (uint32_t)lq * 16u;
    uint32_t browo  = (uint32_t)(l7 + lq * 8) * 256u;
    uint32_t brx    = ((uint32_t)l7 & 7u) << 4;
    uint32_t blk    = (uint32_t)lh * 16u;

    int gid = lane >> 2, tig = lane & 3;
    uint32_t bufb = sb + OFF_B;

    for (int u = 0; u < 4; u++) {
        CP_WAIT0;
        __syncthreads();   // B(u) staged + A tile (epilogue writes) visible

        float acc[64];
#pragma unroll
        for (int i = 0; i < 64; i++) acc[i] = 0.0f;

        if (u == 0) do_unit_mma<5>(a_base, alk, arx, bufb, browo, blk, brx, acc);
        else        do_unit_mma<8>(a_base, alk, arx, bufb, browo, blk, brx, acc);

        __syncthreads();   // all mma reads of A and B done

        // prefetch next unit's weights (hidden under the epilogue below)
        if (u < 3) {
            const char* src = (const char*)g_wimg + (size_t)(u + 1) * 65536;
            for (int i = tid; i < 4096; i += 512)
                CP_ASYNC16(bufb + i * 16, src + (size_t)i * 16);
            CP_COMMIT;
        }

        if (u < 2) {
            int bo = u * 128;
            int rowA = r0w + gid, rowB = rowA + 8;
#pragma unroll
            for (int np = 0; np < 8; np++)
#pragma unroll
                for (int t = 0; t < 2; t++) {
                    int col = np * 16 + t * 8 + 2 * tig;
                    float* c = &acc[(2 * np + t) * 4];
                    float b0v = bias_s[bo + col], b1v = bias_s[bo + col + 1];
                    float v0 = fmaxf(c[0] + b0v, 0.0f), v1 = fmaxf(c[1] + b1v, 0.0f);
                    float v2 = fmaxf(c[2] + b0v, 0.0f), v3 = fmaxf(c[3] + b1v, 0.0f);
                    uint32_t h, l;
                    split2(v0, v1, h, l);
                    { uint32_t o = poff((uint32_t)rowA, (uint32_t)col);
                      *(uint32_t*)(smc + OFF_A + o) = h;
                      *(uint32_t*)(smc + OFF_A + A_LO + o) = l; }
                    split2(v2, v3, h, l);
                    { uint32_t o = poff((uint32_t)rowB, (uint32_t)col);
                      *(uint32_t*)(smc + OFF_A + o) = h;
                      *(uint32_t*)(smc + OFF_A + A_LO + o) = l; }
                }
        } else {
            int half = u - 2;
            int g = wid >> 1;
            unsigned vm = g_valid[m0 + g];
            int bitbase = (wid & 1) * 16;
            bool okA = (vm >> (bitbase + gid)) & 1u;
            bool okB = (vm >> (bitbase + gid + 8)) & 1u;
#pragma unroll
            for (int np = 0; np < 8; np++)
#pragma unroll
                for (int t = 0; t < 2; t++) {
                    int col = np * 16 + t * 8 + 2 * tig;
                    float* c = &acc[(2 * np + t) * 4];
                    float b0v = bias_s[256 + half * 128 + col];
                    float b1v = bias_s[256 + half * 128 + col + 1];
                    float m0v = fmaxf(okA ? fmaxf(c[0] + b0v, 0.0f) : 0.0f,
                                      okB ? fmaxf(c[2] + b0v, 0.0f) : 0.0f);
                    float m1v = fmaxf(okA ? fmaxf(c[1] + b1v, 0.0f) : 0.0f,
                                      okB ? fmaxf(c[3] + b1v, 0.0f) : 0.0f);
#pragma unroll
                    for (int o = 4; o <= 16; o <<= 1) {
                        m0v = fmaxf(m0v, __shfl_xor_sync(0xffffffffu, m0v, o));
                        m1v = fmaxf(m1v, __shfl_xor_sync(0xffffffffu, m1v, o));
                    }
                    if (lane < 4) {
                        wmax[wid * 128 + col]     = m0v;
                        wmax[wid * 128 + col + 1] = m1v;
                    }
                }
            __syncthreads();
            for (int e = tid; e < 1024; e += 512) {
                int gg = e >> 7, col = e & 127;
                float v = fmaxf(wmax[(gg * 2) * 128 + col], wmax[(gg * 2 + 1) * 128 + col]);
                out[(size_t)(m0 + gg) * 256 + half * 128 + col] = v;
            }
        }
    }
}

// ---------------------------------------------------------------------------
extern "C" void kernel_launch(void* const* d_in, const int* in_sizes, int n_in,
                              void* d_out, int out_size)
{
    const float* x     = (const float*)d_in[0];
    const float* pos   = (const float*)d_in[1];
    const int*   batch = (const int*)d_in[2];
    const int*   idx   = (const int*)d_in[3];
    const float* W1 = (const float*)d_in[4];
    const float* b1 = (const float*)d_in[5];
    const float* W2 = (const float*)d_in[6];
    const float* b2 = (const float*)d_in[7];
    const float* W3 = (const float*)d_in[8];
    const float* b3 = (const float*)d_in[9];

    float* out = (float*)d_out;
    int writeAux = (out_size >= MCTR * 256 + MCTR * 3 + MCTR) ? 1 : 0;
    float* posout   = out + MCTR * 256;
    float* batchout = posout + MCTR * 3;

    prep_kernel<<<256, 256>>>(W1, W2, W3);
    knn_kernel<<<MCTR / 8, 256>>>(pos, batch, idx, posout, batchout, writeAux);

    cudaFuncSetAttribute(mlp_kernel, cudaFuncAttributeMaxDynamicSharedMemorySize, SMEM_TOTAL);
    mlp_kernel<<<MCTR / 8, 512, SMEM_TOTAL>>>(x, pos, idx, b1, b2, b3, out);
}

// round 12
// speedup vs baseline: 1.7231x; 1.2434x over previous
#include <cuda_runtime.h>
#include <cuda_fp16.h>
#include <cstdint>

#define NPTS  32768
#define NB    8
#define PPC   4096
#define DIN   64
#define MCTR  8192
#define KNB   32
#define R2    0.04f

#define SENT 0xffffffffffffffffull

__device__ int      g_nbr[MCTR * KNB];
__device__ unsigned g_valid[MCTR];
// 4 units x 32KB fp16 B[n][k] images (pre-swizzled)
__device__ __align__(16) unsigned char g_wimg[4 * 32768];

// ---------------------------------------------------------------------------
// helpers
// ---------------------------------------------------------------------------
__device__ __forceinline__ uint32_t smem_u32(const void* p) {
    uint32_t a;
    asm("{ .reg .u64 t; cvta.to.shared.u64 t, %1; cvt.u32.u64 %0, t; }" : "=r"(a) : "l"(p));
    return a;
}

// swizzled byte offset inside a [rows][128 fp16] plane (256B rows,
// 16B-unit XOR by row&7 -> conflict-free ldmatrix)
__device__ __forceinline__ uint32_t poff(uint32_t r, uint32_t c) {
    return r * 256u + ((c * 2u) ^ ((r & 7u) << 4));
}

// fp16 compensated split of a float pair -> packed hi, lo
__device__ __forceinline__ void split2(float a, float b, uint32_t& hi, uint32_t& lo) {
    __half ha = __float2half_rn(a), hb = __float2half_rn(b);
    float ra = a - __half2float(ha), rb = b - __half2float(hb);
    __half2 H; H.x = ha; H.y = hb;
    __half2 L; L.x = __float2half_rn(ra); L.y = __float2half_rn(rb);
    hi = *(uint32_t*)&H;
    lo = *(uint32_t*)&L;
}

#define LDSM4(a, r0, r1, r2, r3) \
    asm volatile("ldmatrix.sync.aligned.m8n8.x4.shared.b16 {%0,%1,%2,%3}, [%4];" \
        : "=r"(r0), "=r"(r1), "=r"(r2), "=r"(r3) : "r"(a))

__device__ __forceinline__ void mma16816(float* c, uint32_t a0, uint32_t a1, uint32_t a2,
                                         uint32_t a3, uint32_t b0, uint32_t b1) {
    asm volatile("mma.sync.aligned.m16n8k16.row.col.f32.f16.f16.f32 "
        "{%0,%1,%2,%3}, {%4,%5,%6,%7}, {%8,%9}, {%0,%1,%2,%3};"
        : "+f"(c[0]), "+f"(c[1]), "+f"(c[2]), "+f"(c[3])
        : "r"(a0), "r"(a1), "r"(a2), "r"(a3), "r"(b0), "r"(b1));
}

#define CP_ASYNC16(dst, src) \
    asm volatile("cp.async.cg.shared.global [%0], [%1], 16;" :: "r"(dst), "l"(src))
#define CP_COMMIT  asm volatile("cp.async.commit_group;" ::: "memory")
#define CP_WAIT0   asm volatile("cp.async.wait_group 0;" ::: "memory")

// ---------------------------------------------------------------------------
// Weight prep: fp16 W, pre-swizzled B[n][k] image.
// unit 0: W1 (K padded 67->128), 1: W2, 2: W3[:, :128], 3: W3[:, 128:]
// ---------------------------------------------------------------------------
__global__ void prep_kernel(const float* __restrict__ W1, const float* __restrict__ W2,
                            const float* __restrict__ W3) {
    int t = blockIdx.x * blockDim.x + threadIdx.x;   // 65536
    int u = t >> 14, n = (t >> 7) & 127, k = t & 127;
    float w = 0.0f;
    if (u == 0)      { if (k < 67) w = W1[k * 128 + n]; }
    else if (u == 1) w = W2[k * 128 + n];
    else if (u == 2) w = W3[k * 256 + n];
    else             w = W3[k * 256 + 128 + n];
    *(__half*)(g_wimg + u * 32768 + poff(n, k)) = __float2half_rn(w);
}

// ---------------------------------------------------------------------------
// KNN kernel: radius-first filter (valid-top32 == nearest min(32,cnt) points
// with d2 <= R2). Invalid slots -> center index (masked out downstream).
// ---------------------------------------------------------------------------
__device__ __forceinline__ unsigned long long warp_max_ull(unsigned long long v) {
#pragma unroll
    for (int o = 16; o; o >>= 1) {
        unsigned long long t = __shfl_xor_sync(0xffffffffu, v, o);
        v = t > v ? t : v;
    }
    return v;
}

__global__ void knn_kernel(const float* __restrict__ pos,
                           const int* __restrict__ batch,
                           const int* __restrict__ idx,
                           float* __restrict__ posout,
                           float* __restrict__ batchout,
                           int writeAux)
{
    int warp = (blockIdx.x * blockDim.x + threadIdx.x) >> 5;
    int lane = threadIdx.x & 31;
    if (warp >= MCTR) return;

    int ci = idx[warp];
    int b  = batch[ci];
    int cb = b * PPC;

    float c0 = pos[ci * 3 + 0], c1 = pos[ci * 3 + 1], c2 = pos[ci * 3 + 2];
    float cs = c0 * c0 + c1 * c1 + c2 * c2;

    unsigned long long kept   = SENT;
    unsigned long long curmax = SENT;

    for (int base = 0; base < PPC; base += 32) {
        int j = cb + base + lane;
        float p0 = pos[j * 3 + 0], p1 = pos[j * 3 + 1], p2 = pos[j * 3 + 2];
        float ps = p0 * p0 + p1 * p1 + p2 * p2;
        float dt = c0 * p0 + c1 * p1 + c2 * p2;
        float d2 = (cs + ps) - 2.0f * dt;   // bit-identical to reference expansion

        unsigned u   = __float_as_uint(d2);
        unsigned ord = (u & 0x80000000u) ? ~u : (u | 0x80000000u);
        unsigned long long ck = ((unsigned long long)ord << 32) | (unsigned)j;

        unsigned mask = __ballot_sync(0xffffffffu, (d2 <= R2) && (ck < curmax));
        if (mask) {
            while (mask) {
                int s = __ffs(mask) - 1; mask &= mask - 1;
                unsigned long long cand = __shfl_sync(0xffffffffu, ck, s);
                unsigned long long mx = warp_max_ull(kept);
                if (cand < mx) {
                    unsigned who = __ballot_sync(0xffffffffu, kept == mx);
                    if (lane == (__ffs(who) - 1)) kept = cand;
                }
            }
            curmax = warp_max_ull(kept);
        }
    }

    unsigned vm = __ballot_sync(0xffffffffu, kept != SENT);
    int nb = (kept != SENT) ? (int)(kept & 0xffffffffu) : ci;

    g_nbr[warp * KNB + lane] = nb;
    if (lane == 0) g_valid[warp] = vm;

    if (writeAux) {
        if (lane < 3)   posout[warp * 3 + lane] = pos[ci * 3 + lane];
        if (lane == 3)  batchout[warp] = (float)b;
    }
}

// ---------------------------------------------------------------------------
// MLP kernel: mma.sync fp16 2-term compensated (A split, B single),
// fused 3 layers + masked max. 512 threads / 16 warps; 8 centers/block.
// A planes 128KB (hi/lo fp16), single 32KB B buffer.
// ---------------------------------------------------------------------------
#define OFF_A   16384u
#define A_LO    65536u
#define OFF_B   147456u
#define SMEM_TOTAL 180224

template <int KT>
__device__ __forceinline__ void do_unit_mma(uint32_t a_base, uint32_t alk, uint32_t arx,
                                            uint32_t bufb, uint32_t browo, uint32_t blk,
                                            uint32_t brx, float* acc)
{
#pragma unroll
    for (int kt = 0; kt < KT; kt++) {
        uint32_t k2 = (uint32_t)kt * 32u;
        uint32_t aa = a_base + ((k2 + alk) ^ arx);
        uint32_t ah0, ah1, ah2, ah3, al0, al1, al2, al3;
        LDSM4(aa,        ah0, ah1, ah2, ah3);
        LDSM4(aa + A_LO, al0, al1, al2, al3);
#pragma unroll
        for (int np = 0; np < 8; np++) {
            uint32_t ba = bufb + (uint32_t)np * 4096u + browo + ((k2 + blk) ^ brx);
            uint32_t bh0, bh1, bh2, bh3;
            LDSM4(ba, bh0, bh1, bh2, bh3);
            mma16816(&acc[(2 * np)     * 4], ah0, ah1, ah2, ah3, bh0, bh1);
            mma16816(&acc[(2 * np + 1) * 4], ah0, ah1, ah2, ah3, bh2, bh3);
            mma16816(&acc[(2 * np)     * 4], al0, al1, al2, al3, bh0, bh1);
            mma16816(&acc[(2 * np + 1) * 4], al0, al1, al2, al3, bh2, bh3);
        }
    }
}

__global__ void __launch_bounds__(512, 1)
mlp_kernel(const float* __restrict__ x, const float* __restrict__ pos,
           const int* __restrict__ idx,
           const float* __restrict__ b1, const float* __restrict__ b2,
           const float* __restrict__ b3, float* __restrict__ out)
{
    extern __shared__ char smc[];
    float* bias_s = (float*)smc;           // 512 floats
    float* wmax   = (float*)(smc + 2048);  // 16*128 floats
    uint32_t sb = smem_u32(smc);

    int tid = threadIdx.x, wid = tid >> 5, lane = tid & 31;
    int m0 = blockIdx.x * 8;

    // ---------------- phase 0: feature tile + bias + stage W(unit0) --------
    if (tid < 256) {
        int row = tid;
        int nb  = g_nbr[m0 * KNB + row];
        int ci  = idx[m0 + (row >> 5)];
        const float4* xr = (const float4*)(x + nb * DIN);
#pragma unroll
        for (int i = 0; i < 16; i++) {
            float4 v = __ldg(xr + i);
            uint32_t h0, l0, h1, l1;
            split2(v.x, v.y, h0, l0);
            split2(v.z, v.w, h1, l1);
            uint32_t o0 = poff(row, 4 * i), o1 = poff(row, 4 * i + 2);
            *(uint32_t*)(smc + OFF_A + o0)        = h0;
            *(uint32_t*)(smc + OFF_A + A_LO + o0) = l0;
            *(uint32_t*)(smc + OFF_A + o1)        = h1;
            *(uint32_t*)(smc + OFF_A + A_LO + o1) = l1;
        }
        float r0v = pos[nb * 3 + 0] - pos[ci * 3 + 0];
        float r1v = pos[nb * 3 + 1] - pos[ci * 3 + 1];
        float r2v = pos[nb * 3 + 2] - pos[ci * 3 + 2];
        uint32_t h, l;
        split2(r0v, r1v, h, l);
        { uint32_t o = poff(row, 64);
          *(uint32_t*)(smc + OFF_A + o) = h; *(uint32_t*)(smc + OFF_A + A_LO + o) = l; }
        split2(r2v, 0.0f, h, l);
        { uint32_t o = poff(row, 66);
          *(uint32_t*)(smc + OFF_A + o) = h; *(uint32_t*)(smc + OFF_A + A_LO + o) = l; }
        // zero-pad only cols 68..79 (unit 0 reads k<80; epilogue rewrites all)
#pragma unroll
        for (int c = 68; c < 80; c += 2) {
            uint32_t o = poff(row, c);
            *(uint32_t*)(smc + OFF_A + o) = 0u; *(uint32_t*)(smc + OFF_A + A_LO + o) = 0u;
        }
    } else {
        int j = tid - 256;
        if (j < 32)       ((float4*)bias_s)[j] = ((const float4*)b1)[j];
        else if (j < 64)  ((float4*)bias_s)[j] = ((const float4*)b2)[j - 32];
        else if (j < 96)  ((float4*)bias_s)[j] = ((const float4*)b3)[j - 64];
        const char* src = (const char*)g_wimg;
        for (int i = j; i < 2048; i += 256)
            CP_ASYNC16(sb + OFF_B + i * 16, src + (size_t)i * 16);
    }
    CP_COMMIT;

    // per-warp/lane ldmatrix address constants
    int l7 = lane & 7, lh = (lane >> 3) & 1, lq = lane >> 4;
    int r0w = wid * 16;
    uint32_t arow   = (uint32_t)(r0w + l7 + lh * 8);
    uint32_t a_base = sb + OFF_A + arow * 256u;
    uint32_t arx    = (arow & 7u) << 4;
    uint32_t alk    = (uint32_t)lq * 16u;
    uint32_t browo  = (uint32_t)(l7 + lq * 8) * 256u;
    uint32_t brx    = ((uint32_t)l7 & 7u) << 4;
    uint32_t blk    = (uint32_t)lh * 16u;

    int gid = lane >> 2, tig = lane & 3;
    uint32_t bufb = sb + OFF_B;

    for (int u = 0; u < 4; u++) {
        CP_WAIT0;
        __syncthreads();   // B(u) staged + A tile (epilogue writes) visible

        float acc[64];
#pragma unroll
        for (int i = 0; i < 64; i++) acc[i] = 0.0f;

        if (u == 0) do_unit_mma<5>(a_base, alk, arx, bufb, browo, blk, brx, acc);
        else        do_unit_mma<8>(a_base, alk, arx, bufb, browo, blk, brx, acc);

        __syncthreads();   // all mma reads of A and B done

        // prefetch next unit's weights (hidden under the epilogue below)
        if (u < 3) {
            const char* src = (const char*)g_wimg + (size_t)(u + 1) * 32768;
            for (int i = tid; i < 2048; i += 512)
                CP_ASYNC16(bufb + i * 16, src + (size_t)i * 16);
            CP_COMMIT;
        }

        if (u < 2) {
            int bo = u * 128;
            int rowA = r0w + gid, rowB = rowA + 8;
#pragma unroll
            for (int np = 0; np < 8; np++)
#pragma unroll
                for (int t = 0; t < 2; t++) {
                    int col = np * 16 + t * 8 + 2 * tig;
                    float* c = &acc[(2 * np + t) * 4];
                    float b0v = bias_s[bo + col], b1v = bias_s[bo + col + 1];
                    float v0 = fmaxf(c[0] + b0v, 0.0f), v1 = fmaxf(c[1] + b1v, 0.0f);
                    float v2 = fmaxf(c[2] + b0v, 0.0f), v3 = fmaxf(c[3] + b1v, 0.0f);
                    uint32_t h, l;
                    split2(v0, v1, h, l);
                    { uint32_t o = poff((uint32_t)rowA, (uint32_t)col);
                      *(uint32_t*)(smc + OFF_A + o) = h;
                      *(uint32_t*)(smc + OFF_A + A_LO + o) = l; }
                    split2(v2, v3, h, l);
                    { uint32_t o = poff((uint32_t)rowB, (uint32_t)col);
                      *(uint32_t*)(smc + OFF_A + o) = h;
                      *(uint32_t*)(smc + OFF_A + A_LO + o) = l; }
                }
        } else {
            int half = u - 2;
            int g = wid >> 1;
            unsigned vm = g_valid[m0 + g];
            int bitbase = (wid & 1) * 16;
            bool okA = (vm >> (bitbase + gid)) & 1u;
            bool okB = (vm >> (bitbase + gid + 8)) & 1u;
#pragma unroll
            for (int np = 0; np < 8; np++)
#pragma unroll
                for (int t = 0; t < 2; t++) {
                    int col = np * 16 + t * 8 + 2 * tig;
                    float* c = &acc[(2 * np + t) * 4];
                    float b0v = bias_s[256 + half * 128 + col];
                    float b1v = bias_s[256 + half * 128 + col + 1];
                    float m0v = fmaxf(okA ? fmaxf(c[0] + b0v, 0.0f) : 0.0f,
                                      okB ? fmaxf(c[2] + b0v, 0.0f) : 0.0f);
                    float m1v = fmaxf(okA ? fmaxf(c[1] + b1v, 0.0f) : 0.0f,
                                      okB ? fmaxf(c[3] + b1v, 0.0f) : 0.0f);
#pragma unroll
                    for (int o = 4; o <= 16; o <<= 1) {
                        m0v = fmaxf(m0v, __shfl_xor_sync(0xffffffffu, m0v, o));
                        m1v = fmaxf(m1v, __shfl_xor_sync(0xffffffffu, m1v, o));
                    }
                    if (lane < 4) {
                        wmax[wid * 128 + col]     = m0v;
                        wmax[wid * 128 + col + 1] = m1v;
                    }
                }
            __syncthreads();
            for (int e = tid; e < 1024; e += 512) {
                int gg = e >> 7, col = e & 127;
                float v = fmaxf(wmax[(gg * 2) * 128 + col], wmax[(gg * 2 + 1) * 128 + col]);
                out[(size_t)(m0 + gg) * 256 + half * 128 + col] = v;
            }
        }
    }
}

// ---------------------------------------------------------------------------
extern "C" void kernel_launch(void* const* d_in, const int* in_sizes, int n_in,
                              void* d_out, int out_size)
{
    const float* x     = (const float*)d_in[0];
    const float* pos   = (const float*)d_in[1];
    const int*   batch = (const int*)d_in[2];
    const int*   idx   = (const int*)d_in[3];
    const float* W1 = (const float*)d_in[4];
    const float* b1 = (const float*)d_in[5];
    const float* W2 = (const float*)d_in[6];
    const float* b2 = (const float*)d_in[7];
    const float* W3 = (const float*)d_in[8];
    const float* b3 = (const float*)d_in[9];

    float* out = (float*)d_out;
    int writeAux = (out_size >= MCTR * 256 + MCTR * 3 + MCTR) ? 1 : 0;
    float* posout   = out + MCTR * 256;
    float* batchout = posout + MCTR * 3;

    prep_kernel<<<256, 256>>>(W1, W2, W3);
    knn_kernel<<<MCTR / 8, 256>>>(pos, batch, idx, posout, batchout, writeAux);

    cudaFuncSetAttribute(mlp_kernel, cudaFuncAttributeMaxDynamicSharedMemorySize, SMEM_TOTAL);
    mlp_kernel<<<MCTR / 8, 512, SMEM_TOTAL>>>(x, pos, idx, b1, b2, b3, out);
}

// round 16
// speedup vs baseline: 2.0841x; 1.2095x over previous
#include <cuda_runtime.h>
#include <cuda_fp16.h>
#include <cstdint>

#define NPTS  32768
#define NB    8
#define PPC   4096
#define DIN   64
#define MCTR  8192
#define KNB   32
#define R2    0.04f

#define SENT 0xffffffffffffffffull

__device__ int      g_nbr[MCTR * KNB];
__device__ unsigned g_valid[MCTR];
// 4 units x 32KB fp16 B[n][k] images (pre-swizzled)
__device__ __align__(16) unsigned char g_wimg[4 * 32768];

// ---------------------------------------------------------------------------
// helpers
// ---------------------------------------------------------------------------
__device__ __forceinline__ uint32_t smem_u32(const void* p) {
    uint32_t a;
    asm("{ .reg .u64 t; cvta.to.shared.u64 t, %1; cvt.u32.u64 %0, t; }" : "=r"(a) : "l"(p));
    return a;
}

// swizzled byte offset inside a [rows][128 fp16] plane (256B rows,
// 16B-unit XOR by row&7 -> conflict-free ldmatrix)
__device__ __forceinline__ uint32_t poff(uint32_t r, uint32_t c) {
    return r * 256u + ((c * 2u) ^ ((r & 7u) << 4));
}

__device__ __forceinline__ uint32_t h2(float a, float b) {
    __half2 H = __floats2half2_rn(a, b);
    return *(uint32_t*)&H;
}

#define LDSM4(a, r0, r1, r2, r3) \
    asm volatile("ldmatrix.sync.aligned.m8n8.x4.shared.b16 {%0,%1,%2,%3}, [%4];" \
        : "=r"(r0), "=r"(r1), "=r"(r2), "=r"(r3) : "r"(a))

__device__ __forceinline__ void mma16816(float* c, uint32_t a0, uint32_t a1, uint32_t a2,
                                         uint32_t a3, uint32_t b0, uint32_t b1) {
    asm volatile("mma.sync.aligned.m16n8k16.row.col.f32.f16.f16.f32 "
        "{%0,%1,%2,%3}, {%4,%5,%6,%7}, {%8,%9}, {%0,%1,%2,%3};"
        : "+f"(c[0]), "+f"(c[1]), "+f"(c[2]), "+f"(c[3])
        : "r"(a0), "r"(a1), "r"(a2), "r"(a3), "r"(b0), "r"(b1));
}

#define CP_ASYNC16(dst, src) \
    asm volatile("cp.async.cg.shared.global [%0], [%1], 16;" :: "r"(dst), "l"(src))
#define CP_COMMIT  asm volatile("cp.async.commit_group;" ::: "memory")
#define CP_WAIT0   asm volatile("cp.async.wait_group 0;" ::: "memory")

// ---------------------------------------------------------------------------
// Weight prep: fp16 W, pre-swizzled B[n][k] image.
// unit 0: W1 (K padded 67->128), 1: W2, 2: W3[:, :128], 3: W3[:, 128:]
// ---------------------------------------------------------------------------
__global__ void prep_kernel(const float* __restrict__ W1, const float* __restrict__ W2,
                            const float* __restrict__ W3) {
    int t = blockIdx.x * blockDim.x + threadIdx.x;   // 65536
    int u = t >> 14, n = (t >> 7) & 127, k = t & 127;
    float w = 0.0f;
    if (u == 0)      { if (k < 67) w = W1[k * 128 + n]; }
    else if (u == 1) w = W2[k * 128 + n];
    else if (u == 2) w = W3[k * 256 + n];
    else             w = W3[k * 256 + 128 + n];
    *(__half*)(g_wimg + u * 32768 + poff(n, k)) = __float2half_rn(w);
}

// ---------------------------------------------------------------------------
// KNN kernel: radius-first filter (valid-top32 == nearest min(32,cnt) points
// with d2 <= R2). Invalid slots -> center index (masked out downstream).
// ---------------------------------------------------------------------------
__device__ __forceinline__ unsigned long long warp_max_ull(unsigned long long v) {
#pragma unroll
    for (int o = 16; o; o >>= 1) {
        unsigned long long t = __shfl_xor_sync(0xffffffffu, v, o);
        v = t > v ? t : v;
    }
    return v;
}

__global__ void knn_kernel(const float* __restrict__ pos,
                           const int* __restrict__ batch,
                           const int* __restrict__ idx,
                           float* __restrict__ posout,
                           float* __restrict__ batchout,
                           int writeAux)
{
    int warp = (blockIdx.x * blockDim.x + threadIdx.x) >> 5;
    int lane = threadIdx.x & 31;
    if (warp >= MCTR) return;

    int ci = idx[warp];
    int b  = batch[ci];
    int cb = b * PPC;

    float c0 = pos[ci * 3 + 0], c1 = pos[ci * 3 + 1], c2 = pos[ci * 3 + 2];
    float cs = c0 * c0 + c1 * c1 + c2 * c2;

    unsigned long long kept   = SENT;
    unsigned long long curmax = SENT;

    for (int base = 0; base < PPC; base += 32) {
        int j = cb + base + lane;
        float p0 = pos[j * 3 + 0], p1 = pos[j * 3 + 1], p2 = pos[j * 3 + 2];
        float ps = p0 * p0 + p1 * p1 + p2 * p2;
        float dt = c0 * p0 + c1 * p1 + c2 * p2;
        float d2 = (cs + ps) - 2.0f * dt;   // bit-identical to reference expansion

        unsigned u   = __float_as_uint(d2);
        unsigned ord = (u & 0x80000000u) ? ~u : (u | 0x80000000u);
        unsigned long long ck = ((unsigned long long)ord << 32) | (unsigned)j;

        unsigned mask = __ballot_sync(0xffffffffu, (d2 <= R2) && (ck < curmax));
        if (mask) {
            while (mask) {
                int s = __ffs(mask) - 1; mask &= mask - 1;
                unsigned long long cand = __shfl_sync(0xffffffffu, ck, s);
                unsigned long long mx = warp_max_ull(kept);
                if (cand < mx) {
                    unsigned who = __ballot_sync(0xffffffffu, kept == mx);
                    if (lane == (__ffs(who) - 1)) kept = cand;
                }
            }
            curmax = warp_max_ull(kept);
        }
    }

    unsigned vm = __ballot_sync(0xffffffffu, kept != SENT);
    int nb = (kept != SENT) ? (int)(kept & 0xffffffffu) : ci;

    g_nbr[warp * KNB + lane] = nb;
    if (lane == 0) g_valid[warp] = vm;

    if (writeAux) {
        if (lane < 3)   posout[warp * 3 + lane] = pos[ci * 3 + lane];
        if (lane == 3)  batchout[warp] = (float)b;
    }
}

// ---------------------------------------------------------------------------
// MLP kernel: mma.sync fp16 single-precision-per-plane (A and B single fp16),
// fused 3 layers + masked max. 512 threads / 16 warps; 8 centers/block.
// A plane 64KB; ALL weight units (128KB) resident in smem after phase 0.
// ---------------------------------------------------------------------------
#define OFF_A   16384u
#define OFF_W   81920u
#define SMEM_TOTAL 212992

template <int KT>
__device__ __forceinline__ void do_unit_mma(uint32_t a_base, uint32_t alk, uint32_t arx,
                                            uint32_t bufb, uint32_t browo, uint32_t blk,
                                            uint32_t brx, float* acc)
{
#pragma unroll
    for (int kt = 0; kt < KT; kt++) {
        uint32_t k2 = (uint32_t)kt * 32u;
        uint32_t aa = a_base + ((k2 + alk) ^ arx);
        uint32_t a0, a1, a2, a3;
        LDSM4(aa, a0, a1, a2, a3);
#pragma unroll
        for (int np = 0; np < 8; np++) {
            uint32_t ba = bufb + (uint32_t)np * 4096u + browo + ((k2 + blk) ^ brx);
            uint32_t b0, b1, b2, b3;
            LDSM4(ba, b0, b1, b2, b3);
            mma16816(&acc[(2 * np)     * 4], a0, a1, a2, a3, b0, b1);
            mma16816(&acc[(2 * np + 1) * 4], a0, a1, a2, a3, b2, b3);
        }
    }
}

__global__ void __launch_bounds__(512, 1)
mlp_kernel(const float* __restrict__ x, const float* __restrict__ pos,
           const int* __restrict__ idx,
           const float* __restrict__ b1, const float* __restrict__ b2,
           const float* __restrict__ b3, float* __restrict__ out)
{
    extern __shared__ char smc[];
    float* bias_s = (float*)smc;           // 512 floats
    float* wmax   = (float*)(smc + 2048);  // 16*128 floats
    uint32_t sb = smem_u32(smc);

    int tid = threadIdx.x, wid = tid >> 5, lane = tid & 31;
    int m0 = blockIdx.x * 8;

    // ---------------- phase 0: feature tile + bias + stage ALL weights -----
    if (tid < 256) {
        int row = tid;
        int nb  = g_nbr[m0 * KNB + row];
        int ci  = idx[m0 + (row >> 5)];
        const float4* xr = (const float4*)(x + nb * DIN);
#pragma unroll
        for (int i = 0; i < 16; i++) {
            float4 v = __ldg(xr + i);
            *(uint32_t*)(smc + OFF_A + poff(row, 4 * i))     = h2(v.x, v.y);
            *(uint32_t*)(smc + OFF_A + poff(row, 4 * i + 2)) = h2(v.z, v.w);
        }
        float r0v = pos[nb * 3 + 0] - pos[ci * 3 + 0];
        float r1v = pos[nb * 3 + 1] - pos[ci * 3 + 1];
        float r2v = pos[nb * 3 + 2] - pos[ci * 3 + 2];
        *(uint32_t*)(smc + OFF_A + poff(row, 64)) = h2(r0v, r1v);
        *(uint32_t*)(smc + OFF_A + poff(row, 66)) = h2(r2v, 0.0f);
        // zero-pad cols 68..79 (unit 0 reads k<80; epilogue rewrites all)
#pragma unroll
        for (int c = 68; c < 80; c += 2)
            *(uint32_t*)(smc + OFF_A + poff(row, c)) = 0u;
    } else {
        int j = tid - 256;
        if (j < 32)       ((float4*)bias_s)[j] = ((const float4*)b1)[j];
        else if (j < 64)  ((float4*)bias_s)[j] = ((const float4*)b2)[j - 32];
        else if (j < 128) ((float4*)bias_s)[j] = ((const float4*)b3)[j - 64];
        const char* src = (const char*)g_wimg;
        for (int i = j; i < 8192; i += 256)
            CP_ASYNC16(sb + OFF_W + i * 16, src + (size_t)i * 16);
    }
    CP_COMMIT;
    CP_WAIT0;
    __syncthreads();

    // per-warp/lane ldmatrix address constants
    int l7 = lane & 7, lh = (lane >> 3) & 1, lq = lane >> 4;
    int r0w = wid * 16;
    uint32_t arow   = (uint32_t)(r0w + l7 + lh * 8);
    uint32_t a_base = sb + OFF_A + arow * 256u;
    uint32_t arx    = (arow & 7u) << 4;
    uint32_t alk    = (uint32_t)lq * 16u;
    uint32_t browo  = (uint32_t)(l7 + lq * 8) * 256u;
    uint32_t brx    = ((uint32_t)l7 & 7u) << 4;
    uint32_t blk    = (uint32_t)lh * 16u;

    int gid = lane >> 2, tig = lane & 3;

    for (int u = 0; u < 4; u++) {
        uint32_t bufb = sb + OFF_W + (uint32_t)u * 32768u;

        float acc[64];
#pragma unroll
        for (int i = 0; i < 64; i++) acc[i] = 0.0f;

        if (u == 0) do_unit_mma<5>(a_base, alk, arx, bufb, browo, blk, brx, acc);
        else        do_unit_mma<8>(a_base, alk, arx, bufb, browo, blk, brx, acc);

        __syncthreads();   // all mma reads of A done before epilogue rewrites A

        if (u < 2) {
            int bo = u * 128;
            int rowA = r0w + gid, rowB = rowA + 8;
#pragma unroll
            for (int np = 0; np < 8; np++)
#pragma unroll
                for (int t = 0; t < 2; t++) {
                    int col = np * 16 + t * 8 + 2 * tig;
                    float* c = &acc[(2 * np + t) * 4];
                    float b0v = bias_s[bo + col], b1v = bias_s[bo + col + 1];
                    float v0 = fmaxf(c[0] + b0v, 0.0f), v1 = fmaxf(c[1] + b1v, 0.0f);
                    float v2 = fmaxf(c[2] + b0v, 0.0f), v3 = fmaxf(c[3] + b1v, 0.0f);
                    *(uint32_t*)(smc + OFF_A + poff((uint32_t)rowA, (uint32_t)col)) = h2(v0, v1);
                    *(uint32_t*)(smc + OFF_A + poff((uint32_t)rowB, (uint32_t)col)) = h2(v2, v3);
                }
        } else {
            int half = u - 2;
            int g = wid >> 1;
            unsigned vm = g_valid[m0 + g];
            int bitbase = (wid & 1) * 16;
            bool okA = (vm >> (bitbase + gid)) & 1u;
            bool okB = (vm >> (bitbase + gid + 8)) & 1u;
#pragma unroll
            for (int np = 0; np < 8; np++)
#pragma unroll
                for (int t = 0; t < 2; t++) {
                    int col = np * 16 + t * 8 + 2 * tig;
                    float* c = &acc[(2 * np + t) * 4];
                    float b0v = bias_s[256 + half * 128 + col];
                    float b1v = bias_s[256 + half * 128 + col + 1];
                    float m0v = fmaxf(okA ? fmaxf(c[0] + b0v, 0.0f) : 0.0f,
                                      okB ? fmaxf(c[2] + b0v, 0.0f) : 0.0f);
                    float m1v = fmaxf(okA ? fmaxf(c[1] + b1v, 0.0f) : 0.0f,
                                      okB ? fmaxf(c[3] + b1v, 0.0f) : 0.0f);
#pragma unroll
                    for (int o = 4; o <= 16; o <<= 1) {
                        m0v = fmaxf(m0v, __shfl_xor_sync(0xffffffffu, m0v, o));
                        m1v = fmaxf(m1v, __shfl_xor_sync(0xffffffffu, m1v, o));
                    }
                    if (lane < 4) {
                        wmax[wid * 128 + col]     = m0v;
                        wmax[wid * 128 + col + 1] = m1v;
                    }
                }
            __syncthreads();
            for (int e = tid; e < 1024; e += 512) {
                int gg = e >> 7, col = e & 127;
                float v = fmaxf(wmax[(gg * 2) * 128 + col], wmax[(gg * 2 + 1) * 128 + col]);
                out[(size_t)(m0 + gg) * 256 + half * 128 + col] = v;
            }
        }
        __syncthreads();   // epilogue writes (A / wmax reuse) visible before next unit
    }
}

// ---------------------------------------------------------------------------
extern "C" void kernel_launch(void* const* d_in, const int* in_sizes, int n_in,
                              void* d_out, int out_size)
{
    const float* x     = (const float*)d_in[0];
    const float* pos   = (const float*)d_in[1];
    const int*   batch = (const int*)d_in[2];
    const int*   idx   = (const int*)d_in[3];
    const float* W1 = (const float*)d_in[4];
    const float* b1 = (const float*)d_in[5];
    const float* W2 = (const float*)d_in[6];
    const float* b2 = (const float*)d_in[7];
    const float* W3 = (const float*)d_in[8];
    const float* b3 = (const float*)d_in[9];

    float* out = (float*)d_out;
    int writeAux = (out_size >= MCTR * 256 + MCTR * 3 + MCTR) ? 1 : 0;
    float* posout   = out + MCTR * 256;
    float* batchout = posout + MCTR * 3;

    prep_kernel<<<256, 256>>>(W1, W2, W3);
    knn_kernel<<<MCTR / 8, 256>>>(pos, batch, idx, posout, batchout, writeAux);

    cudaFuncSetAttribute(mlp_kernel, cudaFuncAttributeMaxDynamicSharedMemorySize, SMEM_TOTAL);
    mlp_kernel<<<MCTR / 8, 512, SMEM_TOTAL>>>(x, pos, idx, b1, b2, b3, out);
}